// round 6
// baseline (speedup 1.0000x reference)
#include <cuda_runtime.h>

// MultiBCE collapsed + reordered:
//   total = sum_c w(c) * S(c)
//   S(c)  = sum_b clog(b,c),  clog = max(log(1 - |y_true - y_pred|), -100)
//   w(c)  = (1/C) * sum_h lam[h] * La[h,c]
// (arg = 1-|t-p| == t ? p : 1-p exactly, for t in {0,1}, p in [0,1).
//  Masked columns: clog finite (>= -100) and w(c)=0 -> contributes 0,
//  matching the reference's log-clamp behavior.)
//
// Single fused kernel: hot loop accumulates per-column log sums; w is
// computed per-thread from La/lam AFTER the hot loop (L2-resident reads,
// off the register-pressure peak). No prep kernel, no serialized launch.

#define BB 512
#define HH 8
#define CC 8192

#define NBLK   1024
#define NTHR   256
#define CHUNKS 4
#define STRIDE (NBLK * NTHR)   // 262144 float4s; multiple of 2048 ->
                               // column set identical across chunks

__device__ float g_part[NBLK];      // per-block partial sums
__device__ unsigned int g_ticket;   // zero-initialized; last block resets

__global__ void __launch_bounds__(NTHR)
multibce_fused_kernel(const float4* __restrict__ yp4,
                      const float4* __restrict__ yt4,
                      const float4* __restrict__ La4,   // [8][2048] float4
                      const float4* __restrict__ lam4,  // [2] float4
                      float* __restrict__ out) {
    const int tid = blockIdx.x * NTHR + threadIdx.x;   // 0 .. STRIDE-1

    // ── hot loop: 8 front-batched LDG.128, per-column log accumulation ──
    float4 p[CHUNKS], t[CHUNKS];
#pragma unroll
    for (int j = 0; j < CHUNKS; ++j) {
        p[j] = yp4[tid + j * STRIDE];
        t[j] = yt4[tid + j * STRIDE];
    }

    float4 acc = make_float4(0.0f, 0.0f, 0.0f, 0.0f);
#pragma unroll
    for (int j = 0; j < CHUNKS; ++j) {
        float a0 = 1.0f - fabsf(t[j].x - p[j].x);
        float a1 = 1.0f - fabsf(t[j].y - p[j].y);
        float a2 = 1.0f - fabsf(t[j].z - p[j].z);
        float a3 = 1.0f - fabsf(t[j].w - p[j].w);
        // __logf(0) = -inf -> fmaxf gives -100 (torch clamp).
        acc.x += fmaxf(__logf(a0), -100.0f);
        acc.y += fmaxf(__logf(a1), -100.0f);
        acc.z += fmaxf(__logf(a2), -100.0f);
        acc.w += fmaxf(__logf(a3), -100.0f);
    }

    // ── per-thread weights from La/lam (L2/L1-resident, 32KB table) ──
    const int c4 = tid & (CC / 4 - 1);
    const float4 lamA = lam4[0], lamB = lam4[1];
    const float lamv[HH] = {lamA.x, lamA.y, lamA.z, lamA.w,
                            lamB.x, lamB.y, lamB.z, lamB.w};
    float4 wv = make_float4(0.0f, 0.0f, 0.0f, 0.0f);
#pragma unroll
    for (int h = 0; h < HH; ++h) {
        float4 la = La4[h * (CC / 4) + c4];
        wv.x = fmaf(lamv[h], la.x, wv.x);
        wv.y = fmaf(lamv[h], la.y, wv.y);
        wv.z = fmaf(lamv[h], la.z, wv.z);
        wv.w = fmaf(lamv[h], la.w, wv.w);
    }

    const float nscale = -1.0f / (float)CC;  // sign + mean-over-C
    float s = acc.x * wv.x;
    s = fmaf(acc.y, wv.y, s);
    s = fmaf(acc.z, wv.z, s);
    s = fmaf(acc.w, wv.w, s);
    s *= nscale;

    // ── block reduce ──
#pragma unroll
    for (int o = 16; o > 0; o >>= 1)
        s += __shfl_down_sync(0xFFFFFFFFu, s, o);

    __shared__ float smem[NTHR / 32];
    const int lane = threadIdx.x & 31;
    const int wid  = threadIdx.x >> 5;
    if (lane == 0) smem[wid] = s;
    __syncthreads();

    __shared__ bool is_last;
    if (wid == 0) {
        s = (lane < NTHR / 32) ? smem[lane] : 0.0f;
#pragma unroll
        for (int o = 4; o > 0; o >>= 1)
            s += __shfl_down_sync(0xFFFFFFFFu, s, o);
        if (lane == 0) {
            g_part[blockIdx.x] = s;
            __threadfence();                   // partial visible before ticket
            unsigned int tk = atomicAdd(&g_ticket, 1u);
            is_last = (tk == NBLK - 1);
        }
    }
    __syncthreads();

    // ── last block folds the 1024 partials and resets the ticket ──
    if (is_last) {
        float f = 0.0f;
#pragma unroll
        for (int j = 0; j < NBLK / NTHR; ++j)
            f += __ldcg(&g_part[threadIdx.x + j * NTHR]);
#pragma unroll
        for (int o = 16; o > 0; o >>= 1)
            f += __shfl_down_sync(0xFFFFFFFFu, f, o);
        if (lane == 0) smem[wid] = f;
        __syncthreads();
        if (wid == 0) {
            f = (lane < NTHR / 32) ? smem[lane] : 0.0f;
#pragma unroll
            for (int o = 4; o > 0; o >>= 1)
                f += __shfl_down_sync(0xFFFFFFFFu, f, o);
            if (lane == 0) {
                *out = f;
                g_ticket = 0u;   // ready for next graph replay
            }
        }
    }
}

extern "C" void kernel_launch(void* const* d_in, const int* in_sizes, int n_in,
                              void* d_out, int out_size) {
    const float* y_pred = (const float*)d_in[0];  // [512, 8192] f32
    const float* y_true = (const float*)d_in[1];  // [512, 8192] f32
    const float* La     = (const float*)d_in[2];  // [8, 8192]   f32
    const float* lam    = (const float*)d_in[3];  // [8]         f32
    float* out = (float*)d_out;

    multibce_fused_kernel<<<NBLK, NTHR>>>((const float4*)y_pred,
                                          (const float4*)y_true,
                                          (const float4*)La,
                                          (const float4*)lam, out);
}

// round 7
// speedup vs baseline: 1.1518x; 1.1518x over previous
#include <cuda_runtime.h>

// MultiBCE collapsed + reordered, single fused kernel:
//   total = sum_c w(c) * S(c)
//   S(c)  = sum_b clog(b,c),  clog = max(log(1 - |y_true - y_pred|), -100)
//   w(c)  = (1/C) * sum_h lam[h] * La[h,c]
// (arg = 1-|t-p| == t ? p : 1-p exactly for t in {0,1}, p in [0,1);
//  masked columns have w=0 and finite clog -> contribute 0, matching the
//  reference's log-clamp behavior.)
//
// CTA tile = [64 rows x 64 scalar cols] so each CTA needs only 64 w values:
// La traffic is 2KB/CTA (2MB total, L2-resident) computed into smem while
// the 8 front-batched main LDG.128s are in flight. This fixes R6's 32MB
// La-read regression while keeping the single launch.

#define BB 512
#define HH 8
#define CC 8192
#define C4 (CC / 4)          // 2048 float4 columns per row

#define NTHR 256
#define CBLK 128             // column blocks (2048/16 float4)
#define RBLK 8               // row blocks    (512/64)
#define NBLK (RBLK * CBLK)   // 1024
#define COLS4 16             // float4 columns per CTA (= 64 scalar cols)

__device__ float g_part[NBLK];      // per-block partial sums
__device__ unsigned int g_ticket;   // zero-initialized; last block resets

__global__ void __launch_bounds__(NTHR)
multibce_tiled_kernel(const float4* __restrict__ yp4,
                      const float4* __restrict__ yt4,
                      const float* __restrict__ La,    // [8][8192]
                      const float* __restrict__ lam,   // [8]
                      float* __restrict__ out) {
    const int bid = blockIdx.x;
    const int rb  = bid >> 7;            // 0..7   (row block)
    const int cb  = bid & (CBLK - 1);    // 0..127 (col block)
    const int wq  = threadIdx.x >> 5;    // warp 0..7
    const int l   = threadIdx.x & 31;

    // Warp wq, chunk j, lane l -> row = rb*64 + wq*8 + j*2 + (l>>4),
    //                            col4 = cb*16 + (l&15)
    // For fixed j the 32 lanes cover 32 consecutive float4s (512B, 4 lines):
    // fully coalesced. Per-thread col4 is fixed across chunks.
    const int col4 = cb * COLS4 + (l & 15);
    const int row0 = rb * 64 + wq * 8 + (l >> 4);

    // ── front-batch 8 independent LDG.128 ──
    float4 p[4], t[4];
#pragma unroll
    for (int j = 0; j < 4; ++j) {
        const int idx = (row0 + j * 2) * C4 + col4;
        p[j] = yp4[idx];
        t[j] = yt4[idx];
    }

    // ── build the 64-entry w table in smem while loads are in flight ──
    __shared__ float swf[COLS4 * 4];     // 64 scalar weights
    if (threadIdx.x < 64) {
        const int c = cb * 64 + threadIdx.x;
        float s = 0.0f;
#pragma unroll
        for (int h = 0; h < HH; ++h)
            s += lam[h] * La[h * CC + c];
        swf[threadIdx.x] = s;
    }
    __syncthreads();

    // ── per-column clamped-log accumulation ──
    float4 acc = make_float4(0.0f, 0.0f, 0.0f, 0.0f);
#pragma unroll
    for (int j = 0; j < 4; ++j) {
        float a0 = 1.0f - fabsf(t[j].x - p[j].x);
        float a1 = 1.0f - fabsf(t[j].y - p[j].y);
        float a2 = 1.0f - fabsf(t[j].z - p[j].z);
        float a3 = 1.0f - fabsf(t[j].w - p[j].w);
        // __logf(0) = -inf -> fmaxf gives -100 (torch clamp).
        acc.x += fmaxf(__logf(a0), -100.0f);
        acc.y += fmaxf(__logf(a1), -100.0f);
        acc.z += fmaxf(__logf(a2), -100.0f);
        acc.w += fmaxf(__logf(a3), -100.0f);
    }

    // ── weight + scale (one conflict-free 16B LDS per thread) ──
    const float4 wv = ((const float4*)swf)[l & 15];
    float s = acc.x * wv.x;
    s = fmaf(acc.y, wv.y, s);
    s = fmaf(acc.z, wv.z, s);
    s = fmaf(acc.w, wv.w, s);
    s *= -1.0f / (float)CC;              // sign + mean-over-C

    // ── block reduce ──
#pragma unroll
    for (int o = 16; o > 0; o >>= 1)
        s += __shfl_down_sync(0xFFFFFFFFu, s, o);

    __shared__ float smem[NTHR / 32];
    const int lane = threadIdx.x & 31;
    const int wid  = threadIdx.x >> 5;
    if (lane == 0) smem[wid] = s;
    __syncthreads();

    __shared__ bool is_last;
    if (wid == 0) {
        s = (lane < NTHR / 32) ? smem[lane] : 0.0f;
#pragma unroll
        for (int o = 4; o > 0; o >>= 1)
            s += __shfl_down_sync(0xFFFFFFFFu, s, o);
        if (lane == 0) {
            g_part[blockIdx.x] = s;          // spread-address store
            __threadfence();                 // partial visible before ticket
            unsigned int tk = atomicAdd(&g_ticket, 1u);
            is_last = (tk == NBLK - 1);
        }
    }
    __syncthreads();

    // ── last block folds the 1024 partials and resets the ticket ──
    if (is_last) {
        float f = 0.0f;
#pragma unroll
        for (int j = 0; j < NBLK / NTHR; ++j)
            f += __ldcg(&g_part[threadIdx.x + j * NTHR]);
#pragma unroll
        for (int o = 16; o > 0; o >>= 1)
            f += __shfl_down_sync(0xFFFFFFFFu, f, o);
        if (lane == 0) smem[wid] = f;
        __syncthreads();
        if (wid == 0) {
            f = (lane < NTHR / 32) ? smem[lane] : 0.0f;
#pragma unroll
            for (int o = 4; o > 0; o >>= 1)
                f += __shfl_down_sync(0xFFFFFFFFu, f, o);
            if (lane == 0) {
                *out = f;
                g_ticket = 0u;   // ready for next graph replay
            }
        }
    }
}

extern "C" void kernel_launch(void* const* d_in, const int* in_sizes, int n_in,
                              void* d_out, int out_size) {
    const float* y_pred = (const float*)d_in[0];  // [512, 8192] f32
    const float* y_true = (const float*)d_in[1];  // [512, 8192] f32
    const float* La     = (const float*)d_in[2];  // [8, 8192]   f32
    const float* lam    = (const float*)d_in[3];  // [8]         f32
    float* out = (float*)d_out;

    multibce_tiled_kernel<<<NBLK, NTHR>>>((const float4*)y_pred,
                                          (const float4*)y_true,
                                          La, lam, out);
}

// round 9
// speedup vs baseline: 1.3921x; 1.2086x over previous
#include <cuda_runtime.h>

// MultiBCE collapsed form (R1 shape, replication + micro-opt):
//   total = sum_{b,c} e(b,c) * w(c)
//   e(b,c) = -max(log(1 - |y_true - y_pred|), -100)   (y_true in {0,1})
//   w(c)   = (1/C) * sum_h lam[h] * La[h,c]
// Masked entries (La=0) contribute exactly 0 via the log clamp.
//
// Grid-stride loop with 592 blocks: loads are spread through the loop
// (low MLP_p1), which per the B300 multi-CTA-spread model minimizes the
// late-CTA completion tail that front-batched variants suffer from.

#define BB 512
#define HH 8
#define CC 8192

#define NBLK 592
#define NTHR 256

__device__ float g_wneg[CC];  // -w(c): acc = fma(clamped_log, wneg, acc)

__global__ void prep_kernel(const float* __restrict__ La,
                            const float* __restrict__ lam,
                            float* __restrict__ out) {
    int c = blockIdx.x * blockDim.x + threadIdx.x;
    if (c == 0) *out = 0.0f;  // d_out is poisoned; zero before atomics
    if (c < CC) {
        float s = 0.0f;
#pragma unroll
        for (int h = 0; h < HH; ++h)
            s += lam[h] * La[h * CC + c];
        g_wneg[c] = -s * (1.0f / (float)CC);
    }
}

__global__ void __launch_bounds__(NTHR)
bce_reduce_kernel(const float4* __restrict__ yp4,
                  const float4* __restrict__ yt4,
                  float* __restrict__ out) {
    const int N4 = (BB * CC) / 4;               // 1,048,576 float4 groups
    const float4* __restrict__ w4 = (const float4*)g_wneg;

    float acc = 0.0f;
    for (int i = blockIdx.x * blockDim.x + threadIdx.x; i < N4;
         i += gridDim.x * blockDim.x) {
        float4 p = yp4[i];
        float4 t = yt4[i];
        float4 w = w4[i & (CC / 4 - 1)];        // column index = i mod 2048

        // arg = 1 - |t - p| == t ? p : 1-p  (exact for t in {0,1}, p in [0,1))
        float a0 = 1.0f - fabsf(t.x - p.x);
        float a1 = 1.0f - fabsf(t.y - p.y);
        float a2 = 1.0f - fabsf(t.z - p.z);
        float a3 = 1.0f - fabsf(t.w - p.w);

        // __logf(0) = -inf -> fmaxf gives -100, matching the torch clamp.
        float l0 = fmaxf(__logf(a0), -100.0f);
        float l1 = fmaxf(__logf(a1), -100.0f);
        float l2 = fmaxf(__logf(a2), -100.0f);
        float l3 = fmaxf(__logf(a3), -100.0f);

        acc = fmaf(l0, w.x, acc);
        acc = fmaf(l1, w.y, acc);
        acc = fmaf(l2, w.z, acc);
        acc = fmaf(l3, w.w, acc);
    }

    // warp reduce
#pragma unroll
    for (int o = 16; o > 0; o >>= 1)
        acc += __shfl_down_sync(0xFFFFFFFFu, acc, o);

    __shared__ float smem[NTHR / 32];
    const int lane = threadIdx.x & 31;
    const int wid  = threadIdx.x >> 5;
    if (lane == 0) smem[wid] = acc;
    __syncthreads();
    if (wid == 0) {
        acc = (lane < NTHR / 32) ? smem[lane] : 0.0f;
#pragma unroll
        for (int o = 4; o > 0; o >>= 1)
            acc += __shfl_down_sync(0xFFFFFFFFu, acc, o);
        if (lane == 0) atomicAdd(out, acc);
    }
}

extern "C" void kernel_launch(void* const* d_in, const int* in_sizes, int n_in,
                              void* d_out, int out_size) {
    const float* y_pred = (const float*)d_in[0];  // [512, 8192] f32
    const float* y_true = (const float*)d_in[1];  // [512, 8192] f32
    const float* La     = (const float*)d_in[2];  // [8, 8192]   f32
    const float* lam    = (const float*)d_in[3];  // [8]         f32
    float* out = (float*)d_out;

    prep_kernel<<<(CC + 255) / 256, 256>>>(La, lam, out);

    // 592 blocks = 4 CTAs/SM on 148 SMs; grid-stride loop, ~7 iters/thread.
    bce_reduce_kernel<<<NBLK, NTHR>>>((const float4*)y_pred,
                                      (const float4*)y_true, out);
}